// round 1
// baseline (speedup 1.0000x reference)
#include <cuda_runtime.h>
#include <cstdint>
#include <float.h>

#define TWO_PI_F 6.283185307179586f

// Problem dims (compile-time constants for this dataset)
#define M_TOK 16384     // 16 * 32 * 32 tokens
#define K_CIN 2048
#define N_C   768
#define N_CODES 2048

// ---------------- scratch (device globals; no allocation allowed) ----------
__device__ float g_A[(size_t)M_TOK * K_CIN];        // pooled activations [M,K] row-major (128MB)
__device__ float g_xq[(size_t)M_TOK * N_C];         // conv output [M,768] (48MB)
__device__ float g_cbp[(size_t)N_CODES * N_C];      // codebook @ pos_w^T + pos_b (6MB)
__device__ float g_cbn[N_CODES];                    // ||codebook_k||^2
__device__ unsigned long long g_amin[M_TOK];        // packed (enc(dist)<<32 | idx)

// ---------------- init ----------------
__global__ void init_kernel() {
    int i = blockIdx.x * 256 + threadIdx.x;
    if (i < M_TOK) g_amin[i] = ~0ull;
}

// ---------------- 2x2 maxpool: img(16,2048,64,64) -> g_A[t][k] ----------------
// block: (b, hh, 8-channel chunk); smem staging for coalesced reads & writes
__global__ __launch_bounds__(256)
void pool_kernel(const float* __restrict__ img) {
    __shared__ float s[8 * 2 * 64];  // [kc][y][x]
    const int kchunk = blockIdx.x;   // 0..255
    const int hh = blockIdx.y;       // 0..31
    const int b  = blockIdx.z;       // 0..15
    const int tid = threadIdx.x;
    const int k0 = kchunk * 8;
    #pragma unroll
    for (int q = 0; q < 4; q++) {
        int l = tid + 256 * q;              // 0..1023
        int x = l & 63, y = (l >> 6) & 1, kc = l >> 7;
        s[l] = img[((size_t)(b * 2048 + k0 + kc) * 64 + (2 * hh + y)) * 64 + x];
    }
    __syncthreads();
    const int kc = tid & 7, ww = tid >> 3;
    const float* p = &s[kc * 128];
    float v = fmaxf(fmaxf(p[2 * ww], p[2 * ww + 1]),
                    fmaxf(p[64 + 2 * ww], p[64 + 2 * ww + 1]));
    g_A[(size_t)(b * 1024 + hh * 32 + ww) * 2048 + k0 + kc] = v;
}

// ---------------- codebook row norms ----------------
__global__ __launch_bounds__(256)
void cbn_kernel(const float* __restrict__ cb) {
    __shared__ float rb[8];
    const int k = blockIdx.x, tid = threadIdx.x;
    float s = 0.f;
    for (int c = tid; c < 768; c += 256) {
        float v = cb[(size_t)k * 768 + c];
        s = fmaf(v, v, s);
    }
    #pragma unroll
    for (int o = 16; o > 0; o >>= 1) s += __shfl_down_sync(0xffffffffu, s, o);
    if ((tid & 31) == 0) rb[tid >> 5] = s;
    __syncthreads();
    if (tid == 0) {
        float t2 = 0.f;
        #pragma unroll
        for (int q = 0; q < 8; q++) t2 += rb[q];
        g_cbn[k] = t2;
    }
}

// ---------------- SGEMM (TN: A[M,K] rowmajor, B[N,K] rowmajor) ----------------
// MODE 0: C = A*B^T + bias   MODE 1: per-row argmin of (cbn[n] - 2*acc) -> g_amin
#define BM 128
#define BN 128
#define BK 16
#define LDS_ (BM + 4)

__device__ __forceinline__ unsigned int fenc(float f) {
    unsigned int u = __float_as_uint(f);
    return (u & 0x80000000u) ? ~u : (u | 0x80000000u);
}

template<int MODE>
__global__ __launch_bounds__(256, 2)
void sgemm_tn(const float* __restrict__ A, const float* __restrict__ B,
              float* __restrict__ C, const float* __restrict__ bias,
              int M, int N, int K)
{
    __shared__ __align__(16) float sm[2 * BK * LDS_];
    float (*As)[LDS_] = (float(*)[LDS_])sm;
    float (*Bs)[LDS_] = (float(*)[LDS_])(sm + BK * LDS_);

    const int tid = threadIdx.x;
    const int bm = blockIdx.y * BM;
    const int bn = blockIdx.x * BN;
    const int tx = tid & 15, ty = tid >> 4;

    float acc[8][8] = {};

    const int lrow = tid >> 2;            // 0..63
    const int lc4  = (tid & 3) << 2;      // 0,4,8,12
    const float* Ap0 = A + (size_t)(bm + lrow) * K + lc4;
    const float* Ap1 = A + (size_t)(bm + lrow + 64) * K + lc4;
    const float* Bp0 = B + (size_t)(bn + lrow) * K + lc4;
    const float* Bp1 = B + (size_t)(bn + lrow + 64) * K + lc4;

    for (int kt = 0; kt < K; kt += BK) {
        float4 a0 = *(const float4*)(Ap0 + kt);
        float4 a1 = *(const float4*)(Ap1 + kt);
        float4 b0 = *(const float4*)(Bp0 + kt);
        float4 b1 = *(const float4*)(Bp1 + kt);
        __syncthreads();
        As[lc4 + 0][lrow] = a0.x; As[lc4 + 1][lrow] = a0.y;
        As[lc4 + 2][lrow] = a0.z; As[lc4 + 3][lrow] = a0.w;
        As[lc4 + 0][lrow + 64] = a1.x; As[lc4 + 1][lrow + 64] = a1.y;
        As[lc4 + 2][lrow + 64] = a1.z; As[lc4 + 3][lrow + 64] = a1.w;
        Bs[lc4 + 0][lrow] = b0.x; Bs[lc4 + 1][lrow] = b0.y;
        Bs[lc4 + 2][lrow] = b0.z; Bs[lc4 + 3][lrow] = b0.w;
        Bs[lc4 + 0][lrow + 64] = b1.x; Bs[lc4 + 1][lrow + 64] = b1.y;
        Bs[lc4 + 2][lrow + 64] = b1.z; Bs[lc4 + 3][lrow + 64] = b1.w;
        __syncthreads();
        #pragma unroll
        for (int kk = 0; kk < BK; kk++) {
            float4 af0 = *(const float4*)&As[kk][ty * 4];
            float4 af1 = *(const float4*)&As[kk][64 + ty * 4];
            float4 bf0 = *(const float4*)&Bs[kk][tx * 4];
            float4 bf1 = *(const float4*)&Bs[kk][64 + tx * 4];
            float ar[8] = {af0.x, af0.y, af0.z, af0.w, af1.x, af1.y, af1.z, af1.w};
            float br[8] = {bf0.x, bf0.y, bf0.z, bf0.w, bf1.x, bf1.y, bf1.z, bf1.w};
            #pragma unroll
            for (int i = 0; i < 8; i++)
                #pragma unroll
                for (int j = 0; j < 8; j++)
                    acc[i][j] = fmaf(ar[i], br[j], acc[i][j]);
        }
    }
    __syncthreads();

    if (MODE == 0) {
        float bs[8];
        #pragma unroll
        for (int j = 0; j < 8; j++) {
            int n = (j < 4) ? (bn + tx * 4 + j) : (bn + 64 + tx * 4 + (j - 4));
            bs[j] = bias[n];
        }
        #pragma unroll
        for (int i = 0; i < 8; i++) {
            int r = (i < 4) ? (bm + ty * 4 + i) : (bm + 64 + ty * 4 + (i - 4));
            float4 o0, o1;
            o0.x = acc[i][0] + bs[0]; o0.y = acc[i][1] + bs[1];
            o0.z = acc[i][2] + bs[2]; o0.w = acc[i][3] + bs[3];
            o1.x = acc[i][4] + bs[4]; o1.y = acc[i][5] + bs[5];
            o1.z = acc[i][6] + bs[6]; o1.w = acc[i][7] + bs[7];
            float* cp = C + (size_t)r * N;
            *(float4*)(cp + bn + tx * 4) = o0;
            *(float4*)(cp + bn + 64 + tx * 4) = o1;
        }
    } else {
        unsigned long long* red = (unsigned long long*)sm;  // [128][16]
        float cn[8];
        int ncol[8];
        #pragma unroll
        for (int j = 0; j < 8; j++) {
            ncol[j] = (j < 4) ? (bn + tx * 4 + j) : (bn + 64 + tx * 4 + (j - 4));
            cn[j] = g_cbn[ncol[j]];
        }
        #pragma unroll
        for (int i = 0; i < 8; i++) {
            float best = FLT_MAX; int bj = 0;
            #pragma unroll
            for (int j = 0; j < 8; j++) {
                float v = cn[j] - 2.0f * acc[i][j];
                if (v < best) { best = v; bj = ncol[j]; }  // strict < -> lowest idx on ties
            }
            int rloc = (i < 4) ? (ty * 4 + i) : (64 + ty * 4 + (i - 4));
            red[rloc * 16 + tx] = ((unsigned long long)fenc(best) << 32) | (unsigned)bj;
        }
        __syncthreads();
        if (tid < 128) {
            unsigned long long m = red[tid * 16];
            #pragma unroll
            for (int q = 1; q < 16; q++) {
                unsigned long long v = red[tid * 16 + q];
                if (v < m) m = v;
            }
            atomicMin(&g_amin[bm + tid], m);
        }
    }
}

// ---------------- fused epilogue: gate softmax + pos enc + mask + LN + outputs ----
__device__ __forceinline__ float blkSum(float v, float* rb, int tid) {
    #pragma unroll
    for (int o = 16; o > 0; o >>= 1) v += __shfl_down_sync(0xffffffffu, v, o);
    __syncthreads();
    if ((tid & 31) == 0) rb[tid >> 5] = v;
    __syncthreads();
    float r = 0.f;
    #pragma unroll
    for (int q = 0; q < 8; q++) r += rb[q];
    return r;
}

__global__ __launch_bounds__(256)
void epilogue_kernel(const int* __restrict__ vis_hw, const int* __restrict__ tpp,
                     const float* __restrict__ bern,
                     const float* __restrict__ gate_w, const float* __restrict__ gate_b,
                     const float* __restrict__ ln_g, const float* __restrict__ ln_b,
                     const float* __restrict__ mask_emb,
                     float* __restrict__ out, int out_size)
{
    __shared__ float rb[8];
    const int t = blockIdx.x, tid = threadIdx.x;
    const int b = t >> 10, pix = t & 1023, pi = pix >> 5, pj = pix & 31;
    const int imh = vis_hw[2 * b], imw = vis_hw[2 * b + 1];
    const bool rm = (32 * pi < imh), cm = (32 * pj < imw);
    const bool vm = rm && cm;
    const int nr = (imh + 31) >> 5, nc = (imw + 31) >> 5;
    const int idx = (int)(g_amin[t] & 0xffffffffull);

    const int tp = tpp[0];
    const int li = tp / 32, lj = tp % 32;
    const int idx_lab = (int)(g_amin[b * 1024 + li * 32 + lj] & 0xffffffffull);
    const bool vm_lab = (32 * li < imh) && (32 * lj < imw);
    const bool mi = vm && (bern[b] > 0.5f) && vm_lab && (idx == idx_lab);

    // separable positional cumsum closed form
    const float yv = cm ? (TWO_PI_F * (float)min(pi + 1, nr) / ((float)nr + 1e-6f)) : 0.f;
    const float xv = rm ? (TWO_PI_F * (float)min(pj + 1, nc) / ((float)nc + 1e-6f)) : 0.f;

    const float* emb = g_cbp + (size_t)idx * 768;
    const float* xq  = g_xq + (size_t)t * 768;

    float ev[3], qv[3];
    float s0 = 0.f, s1 = 0.f;
    #pragma unroll
    for (int q = 0; q < 3; q++) {
        int c = tid + 256 * q;
        float e = emb[c], x = xq[c];
        ev[q] = e; qv[q] = x;
        s0 += e * gate_w[c] + x * gate_w[768 + c];
        s1 += e * gate_w[1536 + c] + x * gate_w[2304 + c];
    }
    const float S0 = blkSum(s0, rb, tid) + gate_b[0];
    const float S1 = blkSum(s1, rb, tid) + gate_b[1];
    const float mx = fmaxf(S0, S1);
    const float e0 = expf(S0 - mx), e1 = expf(S1 - mx);
    const float inv = 1.0f / (e0 + e1);
    const float p0 = e0 * inv, p1 = e1 * inv;

    const float LCOEF = 0.04797052242f;  // 2*ln(10000)/384
    float f[3];
    #pragma unroll
    for (int q = 0; q < 3; q++) {
        int c = tid + 256 * q;
        int cc = c; float e;
        if (c < 384) { e = yv; } else { e = xv; cc = c - 384; }
        float invdim = expf(-LCOEF * (float)(cc >> 1));
        float val = e * invdim;
        float pos = (cc & 1) ? cosf(val) : sinf(val);
        float fu = mi ? mask_emb[c] : (ev[q] * p0 + qv[q] * p1);
        f[q] = fu + pos;
    }

    const float SUM = blkSum(f[0] + f[1] + f[2], rb, tid);
    const float mu = SUM * (1.0f / 768.0f);
    float d0 = f[0] - mu, d1 = f[1] - mu, d2 = f[2] - mu;
    const float SSQ = blkSum(d0 * d0 + d1 * d1 + d2 * d2, rb, tid);
    const float var = SSQ * (1.0f / 768.0f);
    const float rstd = rsqrtf(var + 1e-5f);

    #pragma unroll
    for (int q = 0; q < 3; q++) {
        int c = tid + 256 * q;
        out[(size_t)t * 768 + c] = (f[q] - mu) * rstd * ln_g[c] + ln_b[c];
    }

    if (tid == 0 && out_size >= 12615680) {
        out[12582912 + t] = vm ? 1.0f : 0.0f;                  // vm_out
        out[12599296 + t] = mi ? (float)idx : -100.0f;         // labels
    }
}

// ---------------- launch ----------------
extern "C" void kernel_launch(void* const* d_in, const int* in_sizes, int n_in,
                              void* d_out, int out_size)
{
    const float* img      = (const float*)d_in[0];
    const int*   vis_hw   = (const int*)d_in[1];
    const int*   tmp_pos  = (const int*)d_in[2];
    const float* bern     = (const float*)d_in[3];
    const float* conv_w   = (const float*)d_in[4];
    const float* conv_b   = (const float*)d_in[5];
    const float* codebook = (const float*)d_in[6];
    const float* pos_w    = (const float*)d_in[7];
    const float* pos_b    = (const float*)d_in[8];
    const float* gate_w   = (const float*)d_in[9];
    const float* gate_b   = (const float*)d_in[10];
    const float* ln_g     = (const float*)d_in[11];
    const float* ln_b     = (const float*)d_in[12];
    const float* mask_emb = (const float*)d_in[13];
    float* out = (float*)d_out;

    void *pA, *pXq, *pCbp;
    cudaGetSymbolAddress(&pA, g_A);
    cudaGetSymbolAddress(&pXq, g_xq);
    cudaGetSymbolAddress(&pCbp, g_cbp);

    init_kernel<<<64, 256>>>();
    pool_kernel<<<dim3(256, 32, 16), 256>>>(img);

    // GEMM1: conv 1x1  (M=16384, N=768, K=2048)
    sgemm_tn<0><<<dim3(768 / BN, M_TOK / BM), 256>>>(
        (const float*)pA, conv_w, (float*)pXq, conv_b, M_TOK, 768, 2048);

    cbn_kernel<<<N_CODES, 256>>>(codebook);

    // GEMM3: codebook projection (M=2048, N=768, K=768) — replaces the per-token pos GEMM
    sgemm_tn<0><<<dim3(768 / BN, N_CODES / BM), 256>>>(
        codebook, pos_w, (float*)pCbp, pos_b, N_CODES, 768, 768);

    // GEMM2: VQ distances + fused argmin (M=16384, N=2048, K=768)
    sgemm_tn<1><<<dim3(N_CODES / BN, M_TOK / BM), 256>>>(
        (const float*)pXq, codebook, nullptr, nullptr, M_TOK, N_CODES, 768);

    epilogue_kernel<<<M_TOK, 256>>>(vis_hw, tmp_pos, bern, gate_w, gate_b,
                                    ln_g, ln_b, mask_emb, out, out_size);
}